// round 8
// baseline (speedup 1.0000x reference)
#include <cuda_runtime.h>
#include <cuda_bf16.h>

// XYLoss: out = (S1 / (B*H*W)) * S2
//   S1 = sum over pixels of [(t0+t1)*softplus(d) - t1*d], d = sigmoid(x1)-sigmoid(x0)
//   S2 = sum(object_mask * box_loss_scale)
// d via HW tanh (2 MUFU/pixel); softplus(d) via Taylor poly on d in (-1,1)
// (max err 2.6e-5 at |d|=1): NO ex2/lg2. Compute = 2 MUFU + ~11 FMA per pixel.

#define HW_   (1024u * 1024u)
#define B_    16u
#define PIX_  (B_ * HW_)        // 16,777,216 pixels
#define NVEC_ (PIX_ / 4u)       // float4 iterations

constexpr int BLOCKS  = 1036;   // 148 SMs * 7 resident blocks = one wave
constexpr int THREADS = 256;

__device__ float2 g_part[BLOCKS];
__device__ unsigned int g_ticket;   // zero-init at load; last block wraps it back to 0

__device__ __forceinline__ float tanh_fast(float x) {
    float r;
    asm("tanh.approx.f32 %0, %1;" : "=f"(r) : "f"(x));   // MUFU.TANH
    return r;
}

__device__ __forceinline__ float per_elem(float x0, float x1, float t0, float t1) {
    float a0 = tanh_fast(0.5f * x0);
    float a1 = tanh_fast(0.5f * x1);
    float d  = 0.5f * (a1 - a0);           // sigmoid(x1)-sigmoid(x0), strictly in (-1,1)
    // softplus(d) = ln2 + d/2 + d^2/8 - d^4/192 + d^6/2880  (|err| <= 2.6e-5 on [-1,1])
    float d2 = d * d;
    float p  = fmaf(d2, 3.472222e-4f, -5.208333e-3f);    // 1/2880, -1/192
    p        = fmaf(d2, p, 0.125f);
    float sp = fmaf(d2, p, fmaf(0.5f, d, 0.69314718f));
    return fmaf(t0 + t1, sp, -t1 * d);
}

__device__ __forceinline__ float4 ldcs4(const float* p) {
    return __ldcs(reinterpret_cast<const float4*>(p));
}

__global__ __launch_bounds__(THREADS, 7) void xyloss_fused(
    const float* __restrict__ mask,
    const float* __restrict__ scale,
    const float* __restrict__ pred,
    const float* __restrict__ truth,
    float* __restrict__ out)
{
    float acc1 = 0.0f;
    float acc2 = 0.0f;

    const unsigned int stride = (unsigned int)(gridDim.x * blockDim.x);
    #pragma unroll 2
    for (unsigned int v = blockIdx.x * blockDim.x + threadIdx.x; v < NVEC_; v += stride) {
        unsigned int idx  = v << 2;                       // pixel index (multiple of 4)
        unsigned int base = idx + (idx & ~(HW_ - 1u));    // = idx + b*HW_

        // Front-batch ALL loads so they are in flight together.
        float4 m  = ldcs4(mask  + idx);
        float4 sc = ldcs4(scale + idx);
        float4 x0 = ldcs4(pred  + base);
        float4 x1 = ldcs4(pred  + base + HW_);
        float4 t0 = ldcs4(truth + base);
        float4 t1 = ldcs4(truth + base + HW_);

        acc2 += m.x * sc.x + m.y * sc.y + m.z * sc.z + m.w * sc.w;

        acc1 += per_elem(x0.x, x1.x, t0.x, t1.x);
        acc1 += per_elem(x0.y, x1.y, t0.y, t1.y);
        acc1 += per_elem(x0.z, x1.z, t0.z, t1.z);
        acc1 += per_elem(x0.w, x1.w, t0.w, t1.w);
    }

    // Warp reduce
    #pragma unroll
    for (int off = 16; off > 0; off >>= 1) {
        acc1 += __shfl_xor_sync(0xFFFFFFFFu, acc1, off);
        acc2 += __shfl_xor_sync(0xFFFFFFFFu, acc2, off);
    }

    // Block reduce across 8 warps
    __shared__ float sh1[THREADS / 32];
    __shared__ float sh2[THREADS / 32];
    __shared__ bool  s_last;
    int wid = threadIdx.x >> 5;
    int lid = threadIdx.x & 31;
    if (lid == 0) { sh1[wid] = acc1; sh2[wid] = acc2; }
    __syncthreads();
    if (threadIdx.x == 0) {
        float b1 = 0.0f, b2 = 0.0f;
        #pragma unroll
        for (int w = 0; w < THREADS / 32; w++) { b1 += sh1[w]; b2 += sh2[w]; }
        g_part[blockIdx.x] = make_float2(b1, b2);
        __threadfence();
        unsigned int t = atomicInc(&g_ticket, BLOCKS - 1);   // wraps to 0 at BLOCKS-1
        s_last = (t == BLOCKS - 1);                          // last arriving block; counter reset
    }
    __syncthreads();

    if (s_last) {
        // Deterministic double-precision combine of all BLOCKS partials.
        double a = 0.0, b = 0.0;
        for (int i = threadIdx.x; i < BLOCKS; i += THREADS) {
            float2 p2 = g_part[i];
            a += (double)p2.x;
            b += (double)p2.y;
        }
        #pragma unroll
        for (int off = 16; off > 0; off >>= 1) {
            a += __shfl_xor_sync(0xFFFFFFFFu, a, off);
            b += __shfl_xor_sync(0xFFFFFFFFu, b, off);
        }
        __shared__ double da[THREADS / 32];
        __shared__ double db[THREADS / 32];
        if (lid == 0) { da[wid] = a; db[wid] = b; }
        __syncthreads();
        if (threadIdx.x == 0) {
            double A = 0.0, Bb = 0.0;
            #pragma unroll
            for (int w = 0; w < THREADS / 32; w++) { A += da[w]; Bb += db[w]; }
            double loss = A / (double)PIX_;
            out[0] = (float)(loss * Bb);
        }
    }
}

extern "C" void kernel_launch(void* const* d_in, const int* in_sizes, int n_in,
                              void* d_out, int out_size)
{
    const float* mask  = (const float*)d_in[0];
    const float* scale = (const float*)d_in[1];
    const float* pred  = (const float*)d_in[2];
    const float* truth = (const float*)d_in[3];
    float* out = (float*)d_out;

    xyloss_fused<<<BLOCKS, THREADS>>>(mask, scale, pred, truth, out);
}

// round 9
// speedup vs baseline: 1.0215x; 1.0215x over previous
#include <cuda_runtime.h>
#include <cuda_bf16.h>

// XYLoss: out = (S1 / (B*H*W)) * S2
//   S1 = sum over pixels of [(t0+t1)*softplus(d) - t1*d], d = sigmoid(x1)-sigmoid(x0)
//   S2 = sum(object_mask * box_loss_scale)
// d via HW tanh (2 MUFU/pixel); softplus(d) via Taylor poly on d in (-1,1).
// __launch_bounds__(256,6): 42-reg budget so ALL 6 float4 loads stay live
// (front-batched MLP). 32-reg configs (R4/R8) serialize the loads -> slower.

#define HW_   (1024u * 1024u)
#define B_    16u
#define PIX_  (B_ * HW_)        // 16,777,216 pixels
#define NVEC_ (PIX_ / 4u)       // float4 iterations

constexpr int BLOCKS  = 888;    // 148 SMs * 6 resident blocks = one wave
constexpr int THREADS = 256;

__device__ float2 g_part[BLOCKS];
__device__ unsigned int g_ticket;   // zero-init at load; last block wraps it back to 0

__device__ __forceinline__ float tanh_fast(float x) {
    float r;
    asm("tanh.approx.f32 %0, %1;" : "=f"(r) : "f"(x));   // MUFU.TANH
    return r;
}

__device__ __forceinline__ float per_elem(float x0, float x1, float t0, float t1) {
    float a0 = tanh_fast(0.5f * x0);
    float a1 = tanh_fast(0.5f * x1);
    float d  = 0.5f * (a1 - a0);           // sigmoid(x1)-sigmoid(x0), strictly in (-1,1)
    // softplus(d) = ln2 + d/2 + d^2/8 - d^4/192 + d^6/2880  (|err| <= 2.6e-5 on [-1,1])
    float d2 = d * d;
    float p  = fmaf(d2, 3.472222e-4f, -5.208333e-3f);    // 1/2880, -1/192
    p        = fmaf(d2, p, 0.125f);
    float sp = fmaf(d2, p, fmaf(0.5f, d, 0.69314718f));
    return fmaf(t0 + t1, sp, -t1 * d);
}

__device__ __forceinline__ float4 ldcs4(const float* p) {
    return __ldcs(reinterpret_cast<const float4*>(p));
}

__global__ __launch_bounds__(THREADS, 6) void xyloss_fused(
    const float* __restrict__ mask,
    const float* __restrict__ scale,
    const float* __restrict__ pred,
    const float* __restrict__ truth,
    float* __restrict__ out)
{
    float acc1 = 0.0f;
    float acc2 = 0.0f;

    const unsigned int stride = (unsigned int)(gridDim.x * blockDim.x);
    #pragma unroll 2
    for (unsigned int v = blockIdx.x * blockDim.x + threadIdx.x; v < NVEC_; v += stride) {
        unsigned int idx  = v << 2;                       // pixel index (multiple of 4)
        unsigned int base = idx + (idx & ~(HW_ - 1u));    // = idx + b*HW_

        // Front-batch ALL loads so they are in flight together.
        float4 m  = ldcs4(mask  + idx);
        float4 sc = ldcs4(scale + idx);
        float4 x0 = ldcs4(pred  + base);
        float4 x1 = ldcs4(pred  + base + HW_);
        float4 t0 = ldcs4(truth + base);
        float4 t1 = ldcs4(truth + base + HW_);

        acc2 += m.x * sc.x + m.y * sc.y + m.z * sc.z + m.w * sc.w;

        acc1 += per_elem(x0.x, x1.x, t0.x, t1.x);
        acc1 += per_elem(x0.y, x1.y, t0.y, t1.y);
        acc1 += per_elem(x0.z, x1.z, t0.z, t1.z);
        acc1 += per_elem(x0.w, x1.w, t0.w, t1.w);
    }

    // Warp reduce
    #pragma unroll
    for (int off = 16; off > 0; off >>= 1) {
        acc1 += __shfl_xor_sync(0xFFFFFFFFu, acc1, off);
        acc2 += __shfl_xor_sync(0xFFFFFFFFu, acc2, off);
    }

    // Block reduce across 8 warps
    __shared__ float sh1[THREADS / 32];
    __shared__ float sh2[THREADS / 32];
    __shared__ bool  s_last;
    int wid = threadIdx.x >> 5;
    int lid = threadIdx.x & 31;
    if (lid == 0) { sh1[wid] = acc1; sh2[wid] = acc2; }
    __syncthreads();
    if (threadIdx.x == 0) {
        float b1 = 0.0f, b2 = 0.0f;
        #pragma unroll
        for (int w = 0; w < THREADS / 32; w++) { b1 += sh1[w]; b2 += sh2[w]; }
        g_part[blockIdx.x] = make_float2(b1, b2);
        __threadfence();
        unsigned int t = atomicInc(&g_ticket, BLOCKS - 1);   // wraps to 0 at BLOCKS-1
        s_last = (t == BLOCKS - 1);                          // last arriving block; counter reset
    }
    __syncthreads();

    if (s_last) {
        // Deterministic double-precision combine of all BLOCKS partials.
        double a = 0.0, b = 0.0;
        for (int i = threadIdx.x; i < BLOCKS; i += THREADS) {
            float2 p2 = g_part[i];
            a += (double)p2.x;
            b += (double)p2.y;
        }
        #pragma unroll
        for (int off = 16; off > 0; off >>= 1) {
            a += __shfl_xor_sync(0xFFFFFFFFu, a, off);
            b += __shfl_xor_sync(0xFFFFFFFFu, b, off);
        }
        __shared__ double da[THREADS / 32];
        __shared__ double db[THREADS / 32];
        if (lid == 0) { da[wid] = a; db[wid] = b; }
        __syncthreads();
        if (threadIdx.x == 0) {
            double A = 0.0, Bb = 0.0;
            #pragma unroll
            for (int w = 0; w < THREADS / 32; w++) { A += da[w]; Bb += db[w]; }
            double loss = A / (double)PIX_;
            out[0] = (float)(loss * Bb);
        }
    }
}

extern "C" void kernel_launch(void* const* d_in, const int* in_sizes, int n_in,
                              void* d_out, int out_size)
{
    const float* mask  = (const float*)d_in[0];
    const float* scale = (const float*)d_in[1];
    const float* pred  = (const float*)d_in[2];
    const float* truth = (const float*)d_in[3];
    float* out = (float*)d_out;

    xyloss_fused<<<BLOCKS, THREADS>>>(mask, scale, pred, truth, out);
}